// round 15
// baseline (speedup 1.0000x reference)
#include <cuda_runtime.h>
#include <math.h>
#include <stdint.h>

#define MS 4096            // square: M == N == 4096
#define RD 16
#define NP 136             // 16*17/2 symmetric pairs
#define KSPLIT 8           // split-K for gram
#define EPSR 1e-5f
#define AST 36             // smem row stride (floats) for mma tiles
#define PST 18             // float2 stride per pair row in hubreg staging

// gram smem layout (bytes)
#define GA0 0
#define GA1 18432
#define GB0 36864
#define GB1 56448
#define GSM 76032

// ---------------- scratch (~90 MB of device globals) ----------------
__device__ float g_Xt[(size_t)MS * MS];              // 64 MB  X transposed
__device__ float g_Apart[(size_t)KSPLIT * MS * NP];  // 17.8 MB gram partials [sp][i][p]
__device__ float g_Ainv[(size_t)MS * RD * RD];       // 4.0 MB
__device__ float g_Pt[(size_t)NP * MS];              // 2.2 MB Pt [p][s] (tf32 values)
__device__ float g_U[MS * RD];
__device__ float g_Vt[MS * RD];                      // V transposed: [n][r]
__device__ float g_cntc[MS];
__device__ float g_cntr[MS];
__device__ float g_coef[4];                          // c, lamda, mu, alpha

__device__ __forceinline__ uint32_t smem_u32(const void* p) {
    uint32_t a;
    asm("{ .reg .u64 t; cvta.to.shared.u64 t, %1; cvt.u32.u64 %0, t; }" : "=r"(a) : "l"(p));
    return a;
}
#define CPA16(dst, src) \
    asm volatile("cp.async.ca.shared.global [%0], [%1], 16;" :: "r"(dst), "l"(src))
#define CPA_COMMIT() asm volatile("cp.async.commit_group;" ::: "memory")
#define CPA_WAIT1()  asm volatile("cp.async.wait_group 1;" ::: "memory")
#define CPA_WAIT0()  asm volatile("cp.async.wait_group 0;" ::: "memory")

// ---- packed fp32x2 helpers ----
__device__ __forceinline__ unsigned long long pack2(float lo, float hi) {
    unsigned long long r;
    asm("mov.b64 %0, {%1, %2};" : "=l"(r) : "f"(lo), "f"(hi));
    return r;
}
__device__ __forceinline__ void unpack2(unsigned long long v, float& lo, float& hi) {
    asm("mov.b64 {%0, %1}, %2;" : "=f"(lo), "=f"(hi) : "l"(v));
}
__device__ __forceinline__ void fma2(unsigned long long& d, unsigned long long a,
                                     unsigned long long b) {
    asm("fma.rn.f32x2 %0, %1, %2, %0;" : "+l"(d) : "l"(a), "l"(b));
}

// ---------------- setup: copy U, transpose V ----------------
__global__ void k_setup(const float* __restrict__ U, const float* __restrict__ V) {
    int tid = blockIdx.x * 256 + threadIdx.x;
    g_U[tid] = U[tid];
    int n = tid >> 4, r = tid & 15;
    g_Vt[tid] = V[r * MS + n];
}

// ---------------- X transpose (32x32 tiles) ----------------
__global__ void k_transpose(const float* __restrict__ X) {
    __shared__ float tile[32][33];
    int x = blockIdx.x * 32 + threadIdx.x;
    int y0 = blockIdx.y * 32;
    #pragma unroll
    for (int j = threadIdx.y; j < 32; j += 8)
        tile[j][threadIdx.x] = X[(size_t)(y0 + j) * MS + x];
    __syncthreads();
    int xo = blockIdx.y * 32 + threadIdx.x;
    int yo0 = blockIdx.x * 32;
    #pragma unroll
    for (int j = threadIdx.y; j < 32; j += 8)
        g_Xt[(size_t)(yo0 + j) * MS + xo] = tile[threadIdx.x][j];
}

// ---------------- initial P build from g_U ----------------
__global__ void k_P() {
    int s = blockIdx.x * 256 + threadIdx.x;
    int plo = blockIdx.y * 34, phi = plo + 34;
    float u[RD];
    const float4* f4 = (const float4*)(g_U + s * RD);
    #pragma unroll
    for (int q = 0; q < 4; q++) {
        float4 v = f4[q];
        u[q * 4 + 0] = v.x; u[q * 4 + 1] = v.y; u[q * 4 + 2] = v.z; u[q * 4 + 3] = v.w;
    }
    #pragma unroll
    for (int r = 0; r < RD; r++) {
        #pragma unroll
        for (int c2 = 0; c2 <= r; c2++) {
            int pidx = r * (r + 1) / 2 + c2;
            if (pidx >= plo && pidx < phi) {
                float v = u[r] * u[c2];
                uint32_t t;
                asm("cvt.rna.tf32.f32 %0, %1;" : "=r"(t) : "f"(v));
                g_Pt[(size_t)pidx * MS + s] = __uint_as_float(t);
            }
        }
    }
}

// ---------------- tf32 mma.sync Gram with cp.async double buffering ----------------
__device__ __forceinline__ void mma_tf32(float* c, const uint32_t* a, uint32_t b0, uint32_t b1) {
    asm volatile(
        "mma.sync.aligned.m16n8k8.row.col.f32.tf32.tf32.f32 "
        "{%0,%1,%2,%3}, {%4,%5,%6,%7}, {%8,%9}, {%0,%1,%2,%3};"
        : "+f"(c[0]), "+f"(c[1]), "+f"(c[2]), "+f"(c[3])
        : "r"(a[0]), "r"(a[1]), "r"(a[2]), "r"(a[3]), "r"(b0), "r"(b1));
}

__global__ __launch_bounds__(256, 2) void k_gram(const float* __restrict__ D) {
    extern __shared__ char sm[];
    uint32_t sb = smem_u32(sm);
    int tx = threadIdx.x, wid = tx >> 5, lane = tx & 31;
    int g = lane >> 2, tig = lane & 3;
    int wm = wid & 3, wn = wid >> 2;
    int j0 = blockIdx.x * 128;
    int sbase = blockIdx.y * (MS / KSPLIT);
    int nbase = wn * 9;
    int ntiles = wn ? 8 : 9;
    const int NCH = (MS / KSPLIT) / 32;   // 16 chunks

    auto issue = [&](int ch, int b) {
        int s0 = sbase + ch * 32;
        uint32_t ab = sb + (b ? GA1 : GA0);
        uint32_t bb = sb + (b ? GB1 : GB0);
        int rA = tx >> 3, s4 = (tx & 7) * 4;
        #pragma unroll
        for (int k = 0; k < 4; k++) {
            int row = rA + k * 32;
            CPA16(ab + row * (AST * 4) + s4 * 4,
                  D + (size_t)(j0 + row) * MS + s0 + s4);
        }
        #pragma unroll
        for (int k = 0; k < 5; k++) {
            int e = tx + k * 256;
            int row = e >> 3, sb4 = (e & 7) * 4;
            if (row < NP)
                CPA16(bb + row * (AST * 4) + sb4 * 4,
                      g_Pt + (size_t)row * MS + s0 + sb4);
        }
        CPA_COMMIT();
    };

    float c[2][9][4];
    #pragma unroll
    for (int tm = 0; tm < 2; tm++)
        #pragma unroll
        for (int nt = 0; nt < 9; nt++)
            #pragma unroll
            for (int q = 0; q < 4; q++) c[tm][nt][q] = 0.f;

    issue(0, 0);
    for (int ch = 0; ch < NCH; ch++) {
        if (ch + 1 < NCH) { issue(ch + 1, (ch + 1) & 1); CPA_WAIT1(); }
        else              { CPA_WAIT0(); }
        __syncthreads();
        const float* As = (const float*)(sm + ((ch & 1) ? GA1 : GA0));
        const float* Bs = (const float*)(sm + ((ch & 1) ? GB1 : GB0));

        #pragma unroll
        for (int t = 0; t < 4; t++) {
            int kc = t * 8;
            uint32_t a[2][4];
            #pragma unroll
            for (int tm = 0; tm < 2; tm++) {
                int r0 = wm * 32 + tm * 16;
                float x0 = As[(r0 + g) * AST + kc + tig];
                float x1 = As[(r0 + g + 8) * AST + kc + tig];
                float x2 = As[(r0 + g) * AST + kc + tig + 4];
                float x3 = As[(r0 + g + 8) * AST + kc + tig + 4];
                a[tm][0] = (x0 != 0.f) ? 0x3F800000u : 0u;
                a[tm][1] = (x1 != 0.f) ? 0x3F800000u : 0u;
                a[tm][2] = (x2 != 0.f) ? 0x3F800000u : 0u;
                a[tm][3] = (x3 != 0.f) ? 0x3F800000u : 0u;
            }
            #pragma unroll
            for (int nt = 0; nt < 9; nt++) {
                if (nt < ntiles) {
                    int n0 = (nbase + nt) * 8;
                    uint32_t b0 = __float_as_uint(Bs[(n0 + g) * AST + kc + tig]);
                    uint32_t b1 = __float_as_uint(Bs[(n0 + g) * AST + kc + tig + 4]);
                    mma_tf32(c[0][nt], a[0], b0, b1);
                    mma_tf32(c[1][nt], a[1], b0, b1);
                }
            }
        }
        __syncthreads();
    }

    #pragma unroll
    for (int tm = 0; tm < 2; tm++) {
        int row = j0 + wm * 32 + tm * 16 + g;
        float* d0 = g_Apart + ((size_t)blockIdx.y * MS + row) * NP;
        float* d1 = g_Apart + ((size_t)blockIdx.y * MS + row + 8) * NP;
        #pragma unroll
        for (int nt = 0; nt < 9; nt++) {
            if (nt < ntiles) {
                int p0 = (nbase + nt) * 8 + 2 * tig;
                d0[p0]     = c[tm][nt][0];
                d0[p0 + 1] = c[tm][nt][1];
                d1[p0]     = c[tm][nt][2];
                d1[p0 + 1] = c[tm][nt][3];
            }
        }
    }
}

// ---------------- warp-per-matrix Gauss-Jordan inversion (+ coef on V-step) ----------------
__global__ __launch_bounds__(256) void k_inv(const float* __restrict__ cc,
                                             const float* __restrict__ lam,
                                             const float* __restrict__ mu,
                                             int layer, int do_coef) {
    if (do_coef && blockIdx.x == 0 && threadIdx.x == 0) {
        double cl = (double)cc[layer];
        double chi1 = erf(sqrt(cl));
        double y = 0.5 * cl * cl;
        double chi3 = erf(sqrt(y)) - 2.0 * sqrt(y) * exp(-y) / sqrt(3.14159265358979323846);
        double alpha = cl * (1.0 - chi1) + 0.5 * chi3;
        g_coef[0] = (float)cl;
        g_coef[1] = lam[layer];
        g_coef[2] = mu[layer];
        g_coef[3] = (float)alpha;
    }
    __shared__ float sA[8][144];
    int tx = threadIdx.x, wid = tx >> 5, lane = tx & 31;
    int i = blockIdx.x * 8 + wid;

    float part[5];
    #pragma unroll
    for (int q = 0; q < 5; q++) part[q] = 0.f;
    #pragma unroll
    for (int sp = 0; sp < KSPLIT; sp++) {
        const float* src = g_Apart + ((size_t)sp * MS + i) * NP;
        #pragma unroll
        for (int q = 0; q < 5; q++) {
            int p = lane + q * 32;
            if (p < NP) part[q] += src[p];
        }
    }
    #pragma unroll
    for (int q = 0; q < 5; q++) {
        int p = lane + q * 32;
        if (p < NP) sA[wid][p] = part[q];
    }
    __syncwarp();

    int r = lane >> 1, h = lane & 1;
    float a[8], v[8];
    #pragma unroll
    for (int j = 0; j < 8; j++) {
        int cc2 = 8 * h + j;
        int rr = max(r, cc2), cs = min(r, cc2);
        a[j] = sA[wid][rr * (rr + 1) / 2 + cs] + ((r == cc2) ? EPSR : 0.f);
        v[j] = (cc2 == r) ? 1.f : 0.f;
    }

    #pragma unroll
    for (int k = 0; k < 16; k++) {
        const int kh = k >> 3, kc = k & 7;
        float piv = __shfl_sync(~0u, a[kc], 2 * k + kh);
        float f   = __shfl_sync(~0u, a[kc], 2 * r + kh);
        float pa[8], pv[8];
        #pragma unroll
        for (int j = 0; j < 8; j++) {
            pa[j] = __shfl_sync(~0u, a[j], 2 * k + h);
            pv[j] = __shfl_sync(~0u, v[j], 2 * k + h);
        }
        float ip = 1.f / piv;
        if (r == k) {
            #pragma unroll
            for (int j = 0; j < 8; j++) { a[j] *= ip; v[j] *= ip; }
        } else {
            float fi = f * ip;
            #pragma unroll
            for (int j = 0; j < 8; j++) { a[j] -= fi * pa[j]; v[j] -= fi * pv[j]; }
        }
    }

    float* dst = g_Ainv + (size_t)i * 256 + r * 16 + 8 * h;
    #pragma unroll
    for (int j = 0; j < 8; j++) dst[j] = v[j];
}

// ---------------- hubreg: thread-per-item, 8 sample-splits per CTA, broadcast F ----------------
// mode 0 (V step): items = columns, D = X  (coalesced across items), F = g_U,  B = g_Vt
// mode 1 (U step): items = rows,    D = Xt (coalesced across items), F = g_Vt, B = g_U
__global__ __launch_bounds__(128, 2) void k_hubreg(const float* __restrict__ D, int mode,
                                                   const float* __restrict__ sg_in,
                                                   float* __restrict__ cnt, int do_cnt,
                                                   int write_P) {
    __shared__ float2 sF2[128 * PST];        // 18 KB pair-interleaved F chunk (256 samples)
    __shared__ float sTp[8][16][RD];         // 8 KB t partials [split][item][r]
    __shared__ float sRed[8][16];            // ssq partials
    __shared__ float sCa[8][16];             // cnt partials
    __shared__ float sB[16][RD];             // beta per item
    __shared__ float sSg[16];                // sigma per item
    __shared__ float sCnt[16];
    int tx = threadIdx.x;
    int item = tx & 15, q = tx >> 4;         // 16 items x 8 splits
    int j0 = blockIdx.x * 16;
    int j = j0 + item;
    const float* F = mode ? g_Vt : g_U;
    float* B = mode ? g_U : g_Vt;
    float cl = g_coef[0], ll = g_coef[1], ml = g_coef[2], alpha = g_coef[3];

    if (tx < 64)
        ((float4*)sB)[tx] = ((const float4*)(B + j0 * RD))[tx];
    if (tx < 16) {
        sSg[tx] = sg_in[0];
        sCnt[tx] = do_cnt ? 0.f : cnt[j0 + tx];
    }
    __syncthreads();

    #pragma unroll 1
    for (int iter = 0; iter < 2; iter++) {
        unsigned long long bp[RD];
        #pragma unroll
        for (int r = 0; r < RD; r++) {
            float bv = sB[item][r];
            bp[r] = pack2(bv, bv);
        }
        float inv_sg = 1.f / sSg[item];
        unsigned long long ssqp = 0ull;
        float ca = 0.f;

        // ---- pass A: ssq (+count) ----
        #pragma unroll 1
        for (int ch = 0; ch < 16; ch++) {
            __syncthreads();
            #pragma unroll
            for (int k = 0; k < 8; k++) {
                int i4 = tx + k * 128;
                float4 f = ((const float4*)(F + ch * 256 * RD))[i4];
                int s = i4 >> 2, rb = (i4 & 3) * 4;
                float* dst = (float*)sF2 + ((s >> 1) * PST + rb) * 2 + (s & 1);
                dst[0] = f.x; dst[2] = f.y; dst[4] = f.z; dst[6] = f.w;
            }
            __syncthreads();
            #pragma unroll 1
            for (int kb = 0; kb < 4; kb++) {
                float2 dr[4];
                #pragma unroll
                for (int k = 0; k < 4; k++) {
                    int s = ch * 256 + 2 * (q * 16 + kb * 4 + k);
                    dr[k].x = D[(size_t)s * MS + j];
                    dr[k].y = D[(size_t)(s + 1) * MS + j];
                }
                #pragma unroll
                for (int k = 0; k < 4; k++) {
                    int pl = q * 16 + kb * 4 + k;
                    const ulonglong2* fp = (const ulonglong2*)(sF2 + pl * PST);
                    unsigned long long dot = 0ull;
                    #pragma unroll
                    for (int r8 = 0; r8 < 8; r8++) {
                        ulonglong2 u = fp[r8];
                        fma2(dot, u.x, bp[2 * r8]);
                        fma2(dot, u.y, bp[2 * r8 + 1]);
                    }
                    float dl, dh;
                    unpack2(dot, dl, dh);
                    float2 d2 = dr[k];
                    if (do_cnt && iter == 0)
                        ca += ((d2.x != 0.f) ? 1.f : 0.f) + ((d2.y != 0.f) ? 1.f : 0.f);
                    float rv0 = (d2.x != 0.f) ? (d2.x - dl) : 0.f;
                    float rv1 = (d2.y != 0.f) ? (d2.y - dh) : 0.f;
                    float p0 = fminf(fmaxf(rv0 * inv_sg, -cl), cl);
                    float p1 = fminf(fmaxf(rv1 * inv_sg, -cl), cl);
                    unsigned long long pp = pack2(p0, p1);
                    fma2(ssqp, pp, pp);
                }
            }
        }
        {
            float lo, hi;
            unpack2(ssqp, lo, hi);
            sRed[q][item] = lo + hi;
            if (do_cnt && iter == 0) sCa[q][item] = ca;
        }
        __syncthreads();
        if (tx < 16) {
            float s = 0.f;
            #pragma unroll
            for (int q8 = 0; q8 < 8; q8++) s += sRed[q8][tx];
            float cv;
            if (do_cnt && iter == 0) {
                cv = 0.f;
                #pragma unroll
                for (int q8 = 0; q8 < 8; q8++) cv += sCa[q8][tx];
                sCnt[tx] = cv;
                cnt[j0 + tx] = cv;
            } else cv = sCnt[tx];
            sSg[tx] = ll * sqrtf(s) * rsqrtf(2.f * cv * alpha);
        }
        __syncthreads();
        float thr = cl * sSg[item];

        // ---- pass B: t accumulation ----
        unsigned long long acc[RD];
        #pragma unroll
        for (int r = 0; r < RD; r++) acc[r] = 0ull;
        #pragma unroll 1
        for (int ch = 0; ch < 16; ch++) {
            __syncthreads();
            #pragma unroll
            for (int k = 0; k < 8; k++) {
                int i4 = tx + k * 128;
                float4 f = ((const float4*)(F + ch * 256 * RD))[i4];
                int s = i4 >> 2, rb = (i4 & 3) * 4;
                float* dst = (float*)sF2 + ((s >> 1) * PST + rb) * 2 + (s & 1);
                dst[0] = f.x; dst[2] = f.y; dst[4] = f.z; dst[6] = f.w;
            }
            __syncthreads();
            #pragma unroll 1
            for (int kb = 0; kb < 4; kb++) {
                float2 dr[4];
                #pragma unroll
                for (int k = 0; k < 4; k++) {
                    int s = ch * 256 + 2 * (q * 16 + kb * 4 + k);
                    dr[k].x = D[(size_t)s * MS + j];
                    dr[k].y = D[(size_t)(s + 1) * MS + j];
                }
                #pragma unroll
                for (int k = 0; k < 4; k++) {
                    int pl = q * 16 + kb * 4 + k;
                    const ulonglong2* fp = (const ulonglong2*)(sF2 + pl * PST);
                    ulonglong2 u[8];
                    #pragma unroll
                    for (int r8 = 0; r8 < 8; r8++) u[r8] = fp[r8];
                    unsigned long long dot = 0ull;
                    #pragma unroll
                    for (int r8 = 0; r8 < 8; r8++) {
                        fma2(dot, u[r8].x, bp[2 * r8]);
                        fma2(dot, u[r8].y, bp[2 * r8 + 1]);
                    }
                    float dl, dh;
                    unpack2(dot, dl, dh);
                    float2 d2 = dr[k];
                    float rv0 = (d2.x != 0.f) ? (d2.x - dl) : 0.f;
                    float rv1 = (d2.y != 0.f) ? (d2.y - dh) : 0.f;
                    unsigned long long pc = pack2(fminf(fmaxf(rv0, -thr), thr),
                                                  fminf(fmaxf(rv1, -thr), thr));
                    #pragma unroll
                    for (int r8 = 0; r8 < 8; r8++) {
                        fma2(acc[2 * r8],     u[r8].x, pc);
                        fma2(acc[2 * r8 + 1], u[r8].y, pc);
                    }
                }
            }
        }
        #pragma unroll
        for (int r = 0; r < RD; r++) {
            float lo, hi;
            unpack2(acc[r], lo, hi);
            sTp[q][item][r] = lo + hi;
        }
        __syncthreads();
        // reduce t over splits: 256 entries, 128 threads x 2
        #pragma unroll
        for (int e0 = 0; e0 < 2; e0++) {
            int e = tx + e0 * 128;
            int it2 = e & 15, r2 = e >> 4;
            float s = 0.f;
            #pragma unroll
            for (int q8 = 0; q8 < 8; q8++) s += sTp[q8][it2][r2];
            sTp[0][it2][r2] = s;
        }
        __syncthreads();
        // delta: 4 warps x 2 rounds x 2 items (half-warp each)
        {
            int w = tx >> 5, lane = tx & 31, rr = lane & 15;
            #pragma unroll
            for (int rd = 0; rd < 2; rd++) {
                int it2 = w * 4 + rd * 2 + ((lane >= 16) ? 1 : 0);
                const float4* Ai = (const float4*)(g_Ainv + (size_t)(j0 + it2) * 256 + rr * 16);
                float delta = 0.f;
                #pragma unroll
                for (int q4 = 0; q4 < 4; q4++) {
                    float4 a4 = Ai[q4];
                    delta += a4.x * sTp[0][it2][q4 * 4]     + a4.y * sTp[0][it2][q4 * 4 + 1]
                           + a4.z * sTp[0][it2][q4 * 4 + 2] + a4.w * sTp[0][it2][q4 * 4 + 3];
                }
                sB[it2][rr] += ml * delta;
            }
        }
        __syncthreads();
    }

    // ---- write back B ----
    if (tx < 64)
        ((float4*)(B + j0 * RD))[tx] = ((const float4*)sB)[tx];

    // ---- P epilogue: Pt for next step from updated beta ----
    if (write_P) {
        #pragma unroll
        for (int m = 0; m < 17; m++) {
            int p = q * 17 + m;
            int r = 0;
            #pragma unroll
            for (int t2 = 1; t2 < 16; t2++)
                if (t2 * (t2 + 1) / 2 <= p) r = t2;
            int c2 = p - r * (r + 1) / 2;
            float v = sB[item][r] * sB[item][c2];
            uint32_t tv;
            asm("cvt.rna.tf32.f32 %0, %1;" : "=r"(tv) : "f"(v));
            g_Pt[(size_t)p * MS + j] = __uint_as_float(tv);
        }
    }
}

// ---------------- final out = U @ V ----------------
__global__ void k_out(float* __restrict__ out) {
    __shared__ float sU[64 * RD];
    int tx = threadIdx.x;
    int n = blockIdx.x * 256 + tx;
    int m0 = blockIdx.y * 64;
    #pragma unroll
    for (int k = 0; k < 4; k++)
        sU[tx + k * 256] = g_U[m0 * RD + tx + k * 256];
    float v[RD];
    #pragma unroll
    for (int r = 0; r < RD; r++) v[r] = g_Vt[n * RD + r];
    __syncthreads();
    for (int j = 0; j < 64; j++) {
        float dot = 0.f;
        #pragma unroll
        for (int r = 0; r < RD; r++) dot += sU[j * RD + r] * v[r];
        out[(size_t)(m0 + j) * MS + n] = dot;
    }
}

// ---------------- orchestration ----------------
extern "C" void kernel_launch(void* const* d_in, const int* in_sizes, int n_in,
                              void* d_out, int out_size) {
    const float* U_in  = (const float*)d_in[0];
    const float* V_in  = (const float*)d_in[1];
    const float* X     = (const float*)d_in[2];
    const float* c_in  = (const float*)d_in[3];
    const float* l_in  = (const float*)d_in[4];
    const float* m_in  = (const float*)d_in[5];
    const float* sg_in = (const float*)d_in[6];
    float* out = (float*)d_out;

    float* Xt;   { void* p; cudaGetSymbolAddress(&p, g_Xt); Xt = (float*)p; }
    float* cntc; { void* p; cudaGetSymbolAddress(&p, g_cntc); cntc = (float*)p; }
    float* cntr; { void* p; cudaGetSymbolAddress(&p, g_cntr); cntr = (float*)p; }

    cudaFuncSetAttribute(k_gram, cudaFuncAttributeMaxDynamicSharedMemorySize, GSM);

    dim3 b256(256), b128(128);
    dim3 ggram(32, KSPLIT);
    dim3 gP(16, 4);

    k_setup<<<256, 256>>>(U_in, V_in);
    k_transpose<<<dim3(128, 128), dim3(32, 8)>>>(X);
    k_P<<<gP, b256>>>();

    for (int layer = 0; layer < 3; layer++) {
        int dc = (layer == 0) ? 1 : 0;
        // ---- V step: items = columns; gram masks via Xt rows; hubreg reads X ----
        k_gram<<<ggram, b256, GSM>>>(Xt);
        k_inv<<<512, 256>>>(c_in, l_in, m_in, layer, 1);
        k_hubreg<<<256, b128>>>(X, 0, sg_in, cntc, dc, 1);
        // ---- U step: items = rows; gram masks via X rows; hubreg reads Xt ----
        k_gram<<<ggram, b256, GSM>>>(X);
        k_inv<<<512, 256>>>(c_in, l_in, m_in, layer, 0);
        k_hubreg<<<256, b128>>>(Xt, 1, sg_in, cntr, dc, 1);
    }

    k_out<<<dim3(16, 64), 256>>>(out);
}

// round 16
// speedup vs baseline: 1.1725x; 1.1725x over previous
#include <cuda_runtime.h>
#include <math.h>
#include <stdint.h>

#define MS 4096            // square: M == N == 4096
#define RD 16
#define NP 136             // 16*17/2 symmetric pairs
#define KSPLIT 8           // split-K for gram
#define EPSR 1e-5f
#define AST 36             // smem row stride (floats) for mma tiles
#define PST 18             // float2 stride per pair row in hubreg staging

// gram smem layout (bytes)
#define GA0 0
#define GA1 18432
#define GB0 36864
#define GB1 56448
#define GSM 76032

// ---------------- scratch (~90 MB of device globals) ----------------
__device__ float g_Xt[(size_t)MS * MS];              // 64 MB  X transposed
__device__ float g_Apart[(size_t)KSPLIT * MS * NP];  // 17.8 MB gram partials [sp][i][p]
__device__ float g_Ainv[(size_t)MS * RD * RD];       // 4.0 MB
__device__ float g_Pt[(size_t)NP * MS];              // 2.2 MB Pt [p][s] (tf32 values)
__device__ float g_U[MS * RD];
__device__ float g_Vt[MS * RD];                      // V transposed: [n][r]
__device__ float g_cntc[MS];
__device__ float g_cntr[MS];
__device__ float g_coef[4];                          // c, lamda, mu, alpha

__device__ __forceinline__ uint32_t smem_u32(const void* p) {
    uint32_t a;
    asm("{ .reg .u64 t; cvta.to.shared.u64 t, %1; cvt.u32.u64 %0, t; }" : "=r"(a) : "l"(p));
    return a;
}
#define CPA16(dst, src) \
    asm volatile("cp.async.ca.shared.global [%0], [%1], 16;" :: "r"(dst), "l"(src))
#define CPA_COMMIT() asm volatile("cp.async.commit_group;" ::: "memory")
#define CPA_WAIT1()  asm volatile("cp.async.wait_group 1;" ::: "memory")
#define CPA_WAIT0()  asm volatile("cp.async.wait_group 0;" ::: "memory")

// ---- packed fp32x2 helpers ----
__device__ __forceinline__ unsigned long long pack2(float lo, float hi) {
    unsigned long long r;
    asm("mov.b64 %0, {%1, %2};" : "=l"(r) : "f"(lo), "f"(hi));
    return r;
}
__device__ __forceinline__ void unpack2(unsigned long long v, float& lo, float& hi) {
    asm("mov.b64 {%0, %1}, %2;" : "=f"(lo), "=f"(hi) : "l"(v));
}
__device__ __forceinline__ void fma2(unsigned long long& d, unsigned long long a,
                                     unsigned long long b) {
    asm("fma.rn.f32x2 %0, %1, %2, %0;" : "+l"(d) : "l"(a), "l"(b));
}
__device__ __forceinline__ unsigned long long add2(unsigned long long a, unsigned long long b) {
    unsigned long long r;
    asm("add.rn.f32x2 %0, %1, %2;" : "=l"(r) : "l"(a), "l"(b));
    return r;
}

// ---------------- setup: copy U, transpose V ----------------
__global__ void k_setup(const float* __restrict__ U, const float* __restrict__ V) {
    int tid = blockIdx.x * 256 + threadIdx.x;
    g_U[tid] = U[tid];
    int n = tid >> 4, r = tid & 15;
    g_Vt[tid] = V[r * MS + n];
}

// ---------------- X transpose (32x32 tiles) ----------------
__global__ void k_transpose(const float* __restrict__ X) {
    __shared__ float tile[32][33];
    int x = blockIdx.x * 32 + threadIdx.x;
    int y0 = blockIdx.y * 32;
    #pragma unroll
    for (int j = threadIdx.y; j < 32; j += 8)
        tile[j][threadIdx.x] = X[(size_t)(y0 + j) * MS + x];
    __syncthreads();
    int xo = blockIdx.y * 32 + threadIdx.x;
    int yo0 = blockIdx.x * 32;
    #pragma unroll
    for (int j = threadIdx.y; j < 32; j += 8)
        g_Xt[(size_t)(yo0 + j) * MS + xo] = tile[threadIdx.x][j];
}

// ---------------- initial P build from g_U (layer0 V-step only) ----------------
__global__ void k_P() {
    int s = blockIdx.x * 256 + threadIdx.x;
    int plo = blockIdx.y * 34, phi = plo + 34;
    float u[RD];
    const float4* f4 = (const float4*)(g_U + s * RD);
    #pragma unroll
    for (int q = 0; q < 4; q++) {
        float4 v = f4[q];
        u[q * 4 + 0] = v.x; u[q * 4 + 1] = v.y; u[q * 4 + 2] = v.z; u[q * 4 + 3] = v.w;
    }
    #pragma unroll
    for (int r = 0; r < RD; r++) {
        #pragma unroll
        for (int c2 = 0; c2 <= r; c2++) {
            int pidx = r * (r + 1) / 2 + c2;
            if (pidx >= plo && pidx < phi) {
                float v = u[r] * u[c2];
                uint32_t t;
                asm("cvt.rna.tf32.f32 %0, %1;" : "=r"(t) : "f"(v));
                g_Pt[(size_t)pidx * MS + s] = __uint_as_float(t);
            }
        }
    }
}

// ---------------- tf32 mma.sync Gram with cp.async double buffering ----------------
__device__ __forceinline__ void mma_tf32(float* c, const uint32_t* a, uint32_t b0, uint32_t b1) {
    asm volatile(
        "mma.sync.aligned.m16n8k8.row.col.f32.tf32.tf32.f32 "
        "{%0,%1,%2,%3}, {%4,%5,%6,%7}, {%8,%9}, {%0,%1,%2,%3};"
        : "+f"(c[0]), "+f"(c[1]), "+f"(c[2]), "+f"(c[3])
        : "r"(a[0]), "r"(a[1]), "r"(a[2]), "r"(a[3]), "r"(b0), "r"(b1));
}

__global__ __launch_bounds__(256, 2) void k_gram(const float* __restrict__ D) {
    extern __shared__ char sm[];
    uint32_t sb = smem_u32(sm);
    int tx = threadIdx.x, wid = tx >> 5, lane = tx & 31;
    int g = lane >> 2, tig = lane & 3;
    int wm = wid & 3, wn = wid >> 2;
    int j0 = blockIdx.x * 128;
    int sbase = blockIdx.y * (MS / KSPLIT);
    int nbase = wn * 9;
    int ntiles = wn ? 8 : 9;
    const int NCH = (MS / KSPLIT) / 32;   // 16 chunks

    auto issue = [&](int ch, int b) {
        int s0 = sbase + ch * 32;
        uint32_t ab = sb + (b ? GA1 : GA0);
        uint32_t bb = sb + (b ? GB1 : GB0);
        int rA = tx >> 3, s4 = (tx & 7) * 4;
        #pragma unroll
        for (int k = 0; k < 4; k++) {
            int row = rA + k * 32;
            CPA16(ab + row * (AST * 4) + s4 * 4,
                  D + (size_t)(j0 + row) * MS + s0 + s4);
        }
        #pragma unroll
        for (int k = 0; k < 5; k++) {
            int e = tx + k * 256;
            int row = e >> 3, sb4 = (e & 7) * 4;
            if (row < NP)
                CPA16(bb + row * (AST * 4) + sb4 * 4,
                      g_Pt + (size_t)row * MS + s0 + sb4);
        }
        CPA_COMMIT();
    };

    float c[2][9][4];
    #pragma unroll
    for (int tm = 0; tm < 2; tm++)
        #pragma unroll
        for (int nt = 0; nt < 9; nt++)
            #pragma unroll
            for (int q = 0; q < 4; q++) c[tm][nt][q] = 0.f;

    issue(0, 0);
    for (int ch = 0; ch < NCH; ch++) {
        if (ch + 1 < NCH) { issue(ch + 1, (ch + 1) & 1); CPA_WAIT1(); }
        else              { CPA_WAIT0(); }
        __syncthreads();
        const float* As = (const float*)(sm + ((ch & 1) ? GA1 : GA0));
        const float* Bs = (const float*)(sm + ((ch & 1) ? GB1 : GB0));

        #pragma unroll
        for (int t = 0; t < 4; t++) {
            int kc = t * 8;
            uint32_t a[2][4];
            #pragma unroll
            for (int tm = 0; tm < 2; tm++) {
                int r0 = wm * 32 + tm * 16;
                float x0 = As[(r0 + g) * AST + kc + tig];
                float x1 = As[(r0 + g + 8) * AST + kc + tig];
                float x2 = As[(r0 + g) * AST + kc + tig + 4];
                float x3 = As[(r0 + g + 8) * AST + kc + tig + 4];
                a[tm][0] = (x0 != 0.f) ? 0x3F800000u : 0u;
                a[tm][1] = (x1 != 0.f) ? 0x3F800000u : 0u;
                a[tm][2] = (x2 != 0.f) ? 0x3F800000u : 0u;
                a[tm][3] = (x3 != 0.f) ? 0x3F800000u : 0u;
            }
            #pragma unroll
            for (int nt = 0; nt < 9; nt++) {
                if (nt < ntiles) {
                    int n0 = (nbase + nt) * 8;
                    uint32_t b0 = __float_as_uint(Bs[(n0 + g) * AST + kc + tig]);
                    uint32_t b1 = __float_as_uint(Bs[(n0 + g) * AST + kc + tig + 4]);
                    mma_tf32(c[0][nt], a[0], b0, b1);
                    mma_tf32(c[1][nt], a[1], b0, b1);
                }
            }
        }
        __syncthreads();
    }

    #pragma unroll
    for (int tm = 0; tm < 2; tm++) {
        int row = j0 + wm * 32 + tm * 16 + g;
        float* d0 = g_Apart + ((size_t)blockIdx.y * MS + row) * NP;
        float* d1 = g_Apart + ((size_t)blockIdx.y * MS + row + 8) * NP;
        #pragma unroll
        for (int nt = 0; nt < 9; nt++) {
            if (nt < ntiles) {
                int p0 = (nbase + nt) * 8 + 2 * tig;
                d0[p0]     = c[tm][nt][0];
                d0[p0 + 1] = c[tm][nt][1];
                d1[p0]     = c[tm][nt][2];
                d1[p0 + 1] = c[tm][nt][3];
            }
        }
    }
}

// ---------------- warp-per-matrix Gauss-Jordan inversion (+ coef on V-step) ----------------
__global__ __launch_bounds__(256) void k_inv(const float* __restrict__ cc,
                                             const float* __restrict__ lam,
                                             const float* __restrict__ mu,
                                             int layer, int do_coef) {
    if (do_coef && blockIdx.x == 0 && threadIdx.x == 0) {
        double cl = (double)cc[layer];
        double chi1 = erf(sqrt(cl));
        double y = 0.5 * cl * cl;
        double chi3 = erf(sqrt(y)) - 2.0 * sqrt(y) * exp(-y) / sqrt(3.14159265358979323846);
        double alpha = cl * (1.0 - chi1) + 0.5 * chi3;
        g_coef[0] = (float)cl;
        g_coef[1] = lam[layer];
        g_coef[2] = mu[layer];
        g_coef[3] = (float)alpha;
    }
    __shared__ float sA[8][144];
    int tx = threadIdx.x, wid = tx >> 5, lane = tx & 31;
    int i = blockIdx.x * 8 + wid;

    float part[5];
    #pragma unroll
    for (int q = 0; q < 5; q++) part[q] = 0.f;
    #pragma unroll
    for (int sp = 0; sp < KSPLIT; sp++) {
        const float* src = g_Apart + ((size_t)sp * MS + i) * NP;
        #pragma unroll
        for (int q = 0; q < 5; q++) {
            int p = lane + q * 32;
            if (p < NP) part[q] += src[p];
        }
    }
    #pragma unroll
    for (int q = 0; q < 5; q++) {
        int p = lane + q * 32;
        if (p < NP) sA[wid][p] = part[q];
    }
    __syncwarp();

    int r = lane >> 1, h = lane & 1;
    float a[8], v[8];
    #pragma unroll
    for (int j = 0; j < 8; j++) {
        int cc2 = 8 * h + j;
        int rr = max(r, cc2), cs = min(r, cc2);
        a[j] = sA[wid][rr * (rr + 1) / 2 + cs] + ((r == cc2) ? EPSR : 0.f);
        v[j] = (cc2 == r) ? 1.f : 0.f;
    }

    #pragma unroll
    for (int k = 0; k < 16; k++) {
        const int kh = k >> 3, kc = k & 7;
        float piv = __shfl_sync(~0u, a[kc], 2 * k + kh);
        float f   = __shfl_sync(~0u, a[kc], 2 * r + kh);
        float pa[8], pv[8];
        #pragma unroll
        for (int j = 0; j < 8; j++) {
            pa[j] = __shfl_sync(~0u, a[j], 2 * k + h);
            pv[j] = __shfl_sync(~0u, v[j], 2 * k + h);
        }
        float ip = 1.f / piv;
        if (r == k) {
            #pragma unroll
            for (int j = 0; j < 8; j++) { a[j] *= ip; v[j] *= ip; }
        } else {
            float fi = f * ip;
            #pragma unroll
            for (int j = 0; j < 8; j++) { a[j] -= fi * pa[j]; v[j] -= fi * pv[j]; }
        }
    }

    float* dst = g_Ainv + (size_t)i * 256 + r * 16 + 8 * h;
    #pragma unroll
    for (int j = 0; j < 8; j++) dst[j] = v[j];
}

// ---------------- fused hubreg: 4 items/warp pass A, 2x2 pass B, P epilogue ----------------
__global__ __launch_bounds__(128, 2) void k_hubreg(const float* __restrict__ D, int mode,
                                                   const float* __restrict__ sg_in,
                                                   float* __restrict__ cnt, int do_cnt,
                                                   int write_P) {
    __shared__ float2 sF2[256 * PST];    // 36 KB pair-interleaved F staging
    __shared__ float sB[4][64];          // per-warp beta for 4 items
    int tx = threadIdx.x, lane = tx & 31, w = tx >> 5;
    int i0 = blockIdx.x * 16 + w * 4;    // 4 items per warp, 256 CTAs
    const float* F = mode ? g_Vt : g_U;
    float* B = mode ? g_U : g_Vt;
    float cl = g_coef[0], ll = g_coef[1], ml = g_coef[2], alpha = g_coef[3];
    float cv[4];
    #pragma unroll
    for (int it = 0; it < 4; it++) cv[it] = do_cnt ? 0.f : cnt[i0 + it];

    #pragma unroll
    for (int it = 0; it < 4; it++)
        if (lane < 16) sB[w][it * 16 + lane] = B[(i0 + it) * RD + lane];
    __syncwarp();
    float sg[4];
    #pragma unroll
    for (int it = 0; it < 4; it++) sg[it] = sg_in[0];

    #pragma unroll 1
    for (int iter = 0; iter < 2; iter++) {
        // ---- pass A: 4 items, ssq (+count on first call iter0) ----
        unsigned long long bpA[64];
        #pragma unroll
        for (int it = 0; it < 4; it++)
            #pragma unroll
            for (int r = 0; r < RD; r++) {
                float bv = sB[w][it * 16 + r];
                bpA[it * 16 + r] = pack2(bv, bv);
            }
        float inv[4];
        #pragma unroll
        for (int it = 0; it < 4; it++) inv[it] = 1.f / sg[it];
        unsigned long long sq[4] = {0ull, 0ull, 0ull, 0ull};
        float ca[4] = {0.f, 0.f, 0.f, 0.f};

        #pragma unroll 1
        for (int t = 0; t < 8; t++) {
            __syncthreads();
            #pragma unroll
            for (int k = 0; k < 16; k++) {
                int i4 = tx + k * 128;
                float4 f = ((const float4*)(F + t * 8192))[i4];
                int s = i4 >> 2, rb = (i4 & 3) * 4;
                float* dst = (float*)sF2 + ((s >> 1) * PST + rb) * 2 + (s & 1);
                dst[0] = f.x; dst[2] = f.y; dst[4] = f.z; dst[6] = f.w;
            }
            __syncthreads();
            #pragma unroll 1
            for (int kb = 0; kb < 4; kb++) {
                float2 dr[4][2];
                #pragma unroll
                for (int it = 0; it < 4; it++)
                    #pragma unroll
                    for (int k = 0; k < 2; k++)
                        dr[it][k] = *(const float2*)&D[(size_t)(i0 + it) * MS + t * 512
                                                       + 2 * (lane + (kb * 2 + k) * 32)];
                #pragma unroll
                for (int k = 0; k < 2; k++) {
                    int p = lane + (kb * 2 + k) * 32;
                    const ulonglong2* fp = (const ulonglong2*)(sF2 + (size_t)p * PST);
                    unsigned long long dt[4] = {0ull, 0ull, 0ull, 0ull};
                    #pragma unroll
                    for (int q = 0; q < 8; q++) {
                        ulonglong2 u = fp[q];
                        #pragma unroll
                        for (int it = 0; it < 4; it++) {
                            fma2(dt[it], u.x, bpA[it * 16 + 2 * q]);
                            fma2(dt[it], u.y, bpA[it * 16 + 2 * q + 1]);
                        }
                    }
                    #pragma unroll
                    for (int it = 0; it < 4; it++) {
                        float dl, dh;
                        unpack2(dt[it], dl, dh);
                        float2 d2 = dr[it][k];
                        if (do_cnt && iter == 0)
                            ca[it] += ((d2.x != 0.f) ? 1.f : 0.f) + ((d2.y != 0.f) ? 1.f : 0.f);
                        float r0 = (d2.x != 0.f) ? (d2.x - dl) : 0.f;
                        float r1 = (d2.y != 0.f) ? (d2.y - dh) : 0.f;
                        float p0 = fminf(fmaxf(r0 * inv[it], -cl), cl);
                        float p1 = fminf(fmaxf(r1 * inv[it], -cl), cl);
                        unsigned long long pp = pack2(p0, p1);
                        fma2(sq[it], pp, pp);
                    }
                }
            }
        }
        #pragma unroll
        for (int it = 0; it < 4; it++) {
            #pragma unroll
            for (int off = 16; off; off >>= 1)
                sq[it] = add2(sq[it], __shfl_xor_sync(~0u, sq[it], off));
            float lo, hi;
            unpack2(sq[it], lo, hi);
            float ssq = lo + hi;
            if (do_cnt && iter == 0) {
                #pragma unroll
                for (int off = 16; off; off >>= 1)
                    ca[it] += __shfl_xor_sync(~0u, ca[it], off);
                cv[it] = ca[it];
                if (lane == 0) cnt[i0 + it] = cv[it];
            }
            sg[it] = ll * sqrtf(ssq) * rsqrtf(2.f * cv[it] * alpha);
        }

        // ---- pass B: two groups of 2 items ----
        #pragma unroll 1
        for (int grp = 0; grp < 2; grp++) {
            int g0 = i0 + 2 * grp, g1 = g0 + 1;
            float th0 = cl * sg[2 * grp], th1 = cl * sg[2 * grp + 1];
            unsigned long long bp0[RD], bp1[RD];
            #pragma unroll
            for (int r = 0; r < RD; r++) {
                float v0 = sB[w][(2 * grp) * 16 + r];
                float v1 = sB[w][(2 * grp + 1) * 16 + r];
                bp0[r] = pack2(v0, v0);
                bp1[r] = pack2(v1, v1);
            }
            unsigned long long ac0[RD], ac1[RD];
            #pragma unroll
            for (int r = 0; r < RD; r++) { ac0[r] = 0ull; ac1[r] = 0ull; }

            #pragma unroll 1
            for (int t = 0; t < 8; t++) {
                __syncthreads();
                #pragma unroll
                for (int k = 0; k < 16; k++) {
                    int i4 = tx + k * 128;
                    float4 f = ((const float4*)(F + t * 8192))[i4];
                    int s = i4 >> 2, rb = (i4 & 3) * 4;
                    float* dst = (float*)sF2 + ((s >> 1) * PST + rb) * 2 + (s & 1);
                    dst[0] = f.x; dst[2] = f.y; dst[4] = f.z; dst[6] = f.w;
                }
                __syncthreads();
                #pragma unroll 1
                for (int kb = 0; kb < 2; kb++) {
                    float2 d0r[4], d1r[4];
                    #pragma unroll
                    for (int k = 0; k < 4; k++) {
                        int p = lane + (kb * 4 + k) * 32;
                        d0r[k] = *(const float2*)&D[(size_t)g0 * MS + t * 512 + 2 * p];
                        d1r[k] = *(const float2*)&D[(size_t)g1 * MS + t * 512 + 2 * p];
                    }
                    #pragma unroll
                    for (int k = 0; k < 4; k++) {
                        int p = lane + (kb * 4 + k) * 32;
                        const ulonglong2* fp = (const ulonglong2*)(sF2 + (size_t)p * PST);
                        ulonglong2 u[8];
                        #pragma unroll
                        for (int q = 0; q < 8; q++) u[q] = fp[q];
                        unsigned long long dt0 = 0ull, dt1 = 0ull;
                        #pragma unroll
                        for (int q = 0; q < 8; q++) {
                            fma2(dt0, u[q].x, bp0[2*q]); fma2(dt0, u[q].y, bp0[2*q+1]);
                            fma2(dt1, u[q].x, bp1[2*q]); fma2(dt1, u[q].y, bp1[2*q+1]);
                        }
                        float a0, a1, b0, b1;
                        unpack2(dt0, a0, a1);
                        unpack2(dt1, b0, b1);
                        float2 d0 = d0r[k], d1 = d1r[k];
                        float r00 = (d0.x != 0.f) ? (d0.x - a0) : 0.f;
                        float r01 = (d0.y != 0.f) ? (d0.y - a1) : 0.f;
                        float r10 = (d1.x != 0.f) ? (d1.x - b0) : 0.f;
                        float r11 = (d1.y != 0.f) ? (d1.y - b1) : 0.f;
                        unsigned long long pc0 = pack2(fminf(fmaxf(r00, -th0), th0),
                                                       fminf(fmaxf(r01, -th0), th0));
                        unsigned long long pc1 = pack2(fminf(fmaxf(r10, -th1), th1),
                                                       fminf(fmaxf(r11, -th1), th1));
                        #pragma unroll
                        for (int q = 0; q < 8; q++) {
                            fma2(ac0[2*q],   u[q].x, pc0);
                            fma2(ac0[2*q+1], u[q].y, pc0);
                            fma2(ac1[2*q],   u[q].x, pc1);
                            fma2(ac1[2*q+1], u[q].y, pc1);
                        }
                    }
                }
            }
            #pragma unroll
            for (int r = 0; r < RD; r++) {
                #pragma unroll
                for (int off = 16; off; off >>= 1) {
                    ac0[r] = add2(ac0[r], __shfl_xor_sync(~0u, ac0[r], off));
                    ac1[r] = add2(ac1[r], __shfl_xor_sync(~0u, ac1[r], off));
                }
            }
            float t0[RD], t1[RD];
            #pragma unroll
            for (int r = 0; r < RD; r++) {
                float lo, hi;
                unpack2(ac0[r], lo, hi); t0[r] = lo + hi;
                unpack2(ac1[r], lo, hi); t1[r] = lo + hi;
            }
            int rr = lane & 15;
            const float4* Ai = (const float4*)(g_Ainv +
                (size_t)(lane < 16 ? g0 : g1) * 256 + rr * 16);
            float delta = 0.f;
            #pragma unroll
            for (int q = 0; q < 4; q++) {
                float4 a4 = Ai[q];
                float w0 = (lane < 16) ? t0[q*4]   : t1[q*4];
                float w1 = (lane < 16) ? t0[q*4+1] : t1[q*4+1];
                float w2 = (lane < 16) ? t0[q*4+2] : t1[q*4+2];
                float w3 = (lane < 16) ? t0[q*4+3] : t1[q*4+3];
                delta += a4.x*w0 + a4.y*w1 + a4.z*w2 + a4.w*w3;
            }
            float db = ml * delta;
            if (lane < 16) sB[w][(2 * grp) * 16 + rr] += db;
            else           sB[w][(2 * grp + 1) * 16 + rr] += db;
            __syncwarp();
        }
    }

    // ---- write back B ----
    #pragma unroll
    for (int it = 0; it < 4; it++)
        if (lane < 16) B[(i0 + it) * RD + lane] = sB[w][it * 16 + lane];

    // ---- P epilogue: Pt for next step from updated beta ----
    if (write_P) {
        #pragma unroll
        for (int sl = 0; sl < 5; sl++) {
            int p = lane + sl * 32;
            if (p < NP) {
                int r = 0;
                #pragma unroll
                for (int q = 1; q < 16; q++)
                    if (q * (q + 1) / 2 <= p) r = q;
                int c2 = p - r * (r + 1) / 2;
                #pragma unroll
                for (int it = 0; it < 4; it++) {
                    float v = sB[w][it * 16 + r] * sB[w][it * 16 + c2];
                    uint32_t tv;
                    asm("cvt.rna.tf32.f32 %0, %1;" : "=r"(tv) : "f"(v));
                    g_Pt[(size_t)p * MS + i0 + it] = __uint_as_float(tv);
                }
            }
        }
    }
}

// ---------------- final out = U @ V ----------------
__global__ void k_out(float* __restrict__ out) {
    __shared__ float sU[64 * RD];
    int tx = threadIdx.x;
    int n = blockIdx.x * 256 + tx;
    int m0 = blockIdx.y * 64;
    #pragma unroll
    for (int k = 0; k < 4; k++)
        sU[tx + k * 256] = g_U[m0 * RD + tx + k * 256];
    float v[RD];
    #pragma unroll
    for (int r = 0; r < RD; r++) v[r] = g_Vt[n * RD + r];
    __syncthreads();
    for (int j = 0; j < 64; j++) {
        float dot = 0.f;
        #pragma unroll
        for (int r = 0; r < RD; r++) dot += sU[j * RD + r] * v[r];
        out[(size_t)(m0 + j) * MS + n] = dot;
    }
}

// ---------------- orchestration ----------------
extern "C" void kernel_launch(void* const* d_in, const int* in_sizes, int n_in,
                              void* d_out, int out_size) {
    const float* U_in  = (const float*)d_in[0];
    const float* V_in  = (const float*)d_in[1];
    const float* X     = (const float*)d_in[2];
    const float* c_in  = (const float*)d_in[3];
    const float* l_in  = (const float*)d_in[4];
    const float* m_in  = (const float*)d_in[5];
    const float* sg_in = (const float*)d_in[6];
    float* out = (float*)d_out;

    float* Xt;   { void* p; cudaGetSymbolAddress(&p, g_Xt); Xt = (float*)p; }
    float* cntc; { void* p; cudaGetSymbolAddress(&p, g_cntc); cntc = (float*)p; }
    float* cntr; { void* p; cudaGetSymbolAddress(&p, g_cntr); cntr = (float*)p; }

    cudaFuncSetAttribute(k_gram, cudaFuncAttributeMaxDynamicSharedMemorySize, GSM);

    dim3 b256(256), b128(128);
    dim3 ggram(32, KSPLIT);
    dim3 gP(16, 4);

    k_setup<<<256, 256>>>(U_in, V_in);
    k_transpose<<<dim3(128, 128), dim3(32, 8)>>>(X);
    k_P<<<gP, b256>>>();

    for (int layer = 0; layer < 3; layer++) {
        int dc = (layer == 0) ? 1 : 0;
        // ---- V step ----
        k_gram<<<ggram, b256, GSM>>>(Xt);
        k_inv<<<512, 256>>>(c_in, l_in, m_in, layer, 1);
        k_hubreg<<<256, b128>>>(Xt, 0, sg_in, cntc, dc, 1);
        // ---- U step ----
        k_gram<<<ggram, b256, GSM>>>(X);
        k_inv<<<512, 256>>>(c_in, l_in, m_in, layer, 0);
        k_hubreg<<<256, b128>>>(X, 1, sg_in, cntr, dc, 1);
    }

    k_out<<<dim3(16, 64), 256>>>(out);
}